// round 10
// baseline (speedup 1.0000x reference)
#include <cuda_runtime.h>

// DTCWT 1D forward, 3 levels, fully fused. x: [64, 1, 2^20] f32.
// Outputs concatenated: lo @0, yh0 @8388608, yh1 @41943040, yh2 @75497472.
// Level 1 computed directly from gmem (overlapping LDG.128, L1 absorbs reuse);
// lo1/lo2 pyramids staged in swizzled shared memory. Target 7 CTAs/SM (36 regs).

#define L0    (1 << 20)
#define L1LEN (L0 >> 1)   // 524288
#define L2LEN (L0 >> 2)   // 262144
#define L3LEN (L0 >> 3)   // 131072
#define BATCH 64

#define TILE_X 8192
#define TILES  (L0 / TILE_X)       // 128
#define N1 (TILE_X / 2)            // 4096
#define N2 (TILE_X / 4)            // 2048
#define N3 (TILE_X / 8)            // 1024
#define H1 24
#define H2 8
#define NTH 256

#define SLO1_SIZE 4160             // (N1+48) padded
#define SLO2_SIZE 2080             // (N2+16) padded
#define SM_TOTAL (SLO1_SIZE + SLO2_SIZE)   // 6240 floats = 24.96 KB

#define OUT_YH0 8388608u
#define OUT_YH1 41943040u
#define OUT_YH2 75497472u

// 2-bit bank swizzle: XOR float-index bits [2,3] with bits [5,6].
__device__ __forceinline__ int SW(int i) { return i ^ ((i >> 3) & 0xC); }

// ---- filters as compile-time immediates (fixed in reference) ----
static __device__ __forceinline__ float conv5_h0o(const float* v) {
    float s = -0.05f * (v[0] + v[4]);
    s = fmaf(0.25f, v[1] + v[3], s);
    s = fmaf(0.6f, v[2], s);
    return s;
}
static __device__ __forceinline__ float conv7_h1o(const float* v) {
    float s = -0.0107143f * (v[0] + v[6]);
    s = fmaf( 0.0535714f, v[1] + v[5], s);
    s = fmaf( 0.2607143f, v[2] + v[4], s);
    s = fmaf(-0.6071429f, v[3], s);
    return s;
}
// h1a[n] = (-1)^n * h0a[13-n]
static __device__ __forceinline__ float conv14_h1a(const float* v) {
    float s = -0.00455690f * v[0];
    s = fmaf( 0.00543948f, v[1],  s);
    s = fmaf( 0.01702522f, v[2],  s);
    s = fmaf(-0.02382538f, v[3],  s);
    s = fmaf(-0.10671180f, v[4],  s);
    s = fmaf(-0.01186609f, v[5],  s);
    s = fmaf( 0.56881042f, v[6],  s);
    s = fmaf(-0.75614564f, v[7],  s);
    s = fmaf( 0.27529538f, v[8],  s);
    s = fmaf( 0.11720389f, v[9],  s);
    s = fmaf(-0.03887280f, v[10], s);
    s = fmaf(-0.03466035f, v[11], s);
    s = fmaf(-0.00388321f, v[12], s);
    s = fmaf(-0.00325314f, v[13], s);
    return s;
}
// lo = conv(h0a), hb = conv(h1b): lo = E + O, hb = O - E (even/odd partial sums).
static __device__ __forceinline__ void conv14_lo_hb(const float* v, float& lo, float& hb) {
    float e =  0.00325314f * v[0];
    e = fmaf( 0.03466035f, v[2],  e);
    e = fmaf(-0.11720389f, v[4],  e);
    e = fmaf( 0.75614564f, v[6],  e);
    e = fmaf( 0.01186609f, v[8],  e);
    e = fmaf( 0.02382538f, v[10], e);
    e = fmaf(-0.00543948f, v[12], e);
    float o = -0.00388321f * v[1];
    o = fmaf(-0.03887280f, v[3],  o);
    o = fmaf( 0.27529538f, v[5],  o);
    o = fmaf( 0.56881042f, v[7],  o);
    o = fmaf(-0.10671180f, v[9],  o);
    o = fmaf( 0.01702522f, v[11], o);
    o = fmaf(-0.00455690f, v[13], o);
    lo = e + o;
    hb = o - e;
}
static __device__ __forceinline__ float conv14_h0a(const float* v) {
    float lo, hb;
    conv14_lo_hb(v, lo, hb);
    return lo;
}

// load 20 floats from swizzled smem, base index ≡ 2 mod 4
static __device__ __forceinline__ void load20(const float* buf, int bi, float* w) {
    *(float2*)(w)      = *(const float2*)(buf + SW(bi));
    *(float4*)(w + 2)  = *(const float4*)(buf + SW(bi + 2));
    *(float4*)(w + 6)  = *(const float4*)(buf + SW(bi + 6));
    *(float4*)(w + 10) = *(const float4*)(buf + SW(bi + 10));
    *(float4*)(w + 14) = *(const float4*)(buf + SW(bi + 14));
    *(float2*)(w + 18) = *(const float2*)(buf + SW(bi + 18));
}

// zero-padded float4 load from x row (element-wise checked; edge tiles only)
static __device__ __forceinline__ float4 ld4_safe(const float* xr, int g) {
    if (g >= 0 && g + 4 <= L0) return *(const float4*)(xr + g);
    float4 v;
    v.x = ((unsigned)(g + 0) < (unsigned)L0) ? xr[g + 0] : 0.0f;
    v.y = ((unsigned)(g + 1) < (unsigned)L0) ? xr[g + 1] : 0.0f;
    v.z = ((unsigned)(g + 2) < (unsigned)L0) ? xr[g + 2] : 0.0f;
    v.w = ((unsigned)(g + 3) < (unsigned)L0) ? xr[g + 3] : 0.0f;
    return v;
}

__global__ __launch_bounds__(NTH, 7) void dtcwt_kernel(const float* __restrict__ x,
                                                       float* __restrict__ out) {
    __shared__ __align__(128) float sm[SM_TOTAL];
    float* slo1 = sm;
    float* slo2 = sm + SLO1_SIZE;

    const int tile = blockIdx.x;   // 0..127
    const int b    = blockIdx.y;   // 0..63
    const int tid  = threadIdx.x;

    const float* xrow = x + (size_t)b * L0;
    const int xbase = tile * TILE_X;

    // ---- Level 1: directly from gmem, 4-wide ----
    const int base1 = tile * N1;
    float* yh0 = out + OUT_YH0 + (size_t)b * L1LEN + base1;

    // lo1 halo (48 entries), zero outside level-1 domain
    if (tid < 2 * H1) {
        int r  = (tid < H1) ? tid : tid + N1;
        int g1 = base1 + (r - H1);
        float v = 0.0f;
        if ((unsigned)g1 < (unsigned)L1LEN) {
            float w[5];
#pragma unroll
            for (int j = 0; j < 5; j++) {
                int p = 2 * g1 - 2 + j;
                w[j] = ((unsigned)p < (unsigned)L0) ? xrow[p] : 0.0f;
            }
            v = conv5_h0o(w);
        }
        slo1[SW(r)] = v;
    }

    const bool interior = (tile > 0) && (tile < TILES - 1);
#pragma unroll 1
    for (int it = 0; it < N1 / (4 * NTH); it++) {   // 4 iters, kept rolled
        int m4 = 4 * tid + it * (4 * NTH);
        int g0 = xbase + 2 * m4 - 4;                 // 16B aligned
        float w[16];
        if (interior) {
            const float4* xp = (const float4*)(xrow + g0);
            *(float4*)(w)      = xp[0];
            *(float4*)(w + 4)  = xp[1];
            *(float4*)(w + 8)  = xp[2];
            *(float4*)(w + 12) = xp[3];
        } else {
            *(float4*)(w)      = ld4_safe(xrow, g0);
            *(float4*)(w + 4)  = ld4_safe(xrow, g0 + 4);
            *(float4*)(w + 8)  = ld4_safe(xrow, g0 + 8);
            *(float4*)(w + 12) = ld4_safe(xrow, g0 + 12);
        }
        // w[j] = x[2*m4 - 4 + j]
        float4 lo, hi;
        lo.x = conv5_h0o(w + 2);  hi.x = conv7_h1o(w + 1);
        lo.y = conv5_h0o(w + 4);  hi.y = conv7_h1o(w + 3);
        lo.z = conv5_h0o(w + 6);  hi.z = conv7_h1o(w + 5);
        lo.w = conv5_h0o(w + 8);  hi.w = conv7_h1o(w + 7);
        *(float4*)(slo1 + SW(m4 + H1)) = lo;
        __stcs((float4*)(yh0 + m4), hi);
    }
    __syncthreads();

    // ---- Level 2 (4-wide, 2 iters) ----
    const int base2 = tile * N2;
    float* yh1 = out + OUT_YH1 + (size_t)b * (2u * L2LEN) + base2;

    if (tid < 2 * H2) {   // lo2 halo (16 entries)
        int r  = (tid < H2) ? tid : tid + N2;
        int g2 = base2 + (r - H2);
        float v = 0.0f;
        if ((unsigned)g2 < (unsigned)L2LEN) {
            float w[14];
#pragma unroll
            for (int j = 0; j < 14; j++) w[j] = slo1[SW(2 * r + 2 + j)];
            v = conv14_h0a(w);
        }
        slo2[SW(r)] = v;
    }
#pragma unroll 1
    for (int it = 0; it < N2 / (4 * NTH); it++) {   // 2 iters, kept rolled
        int m4 = 4 * tid + it * (4 * NTH);
        int bi = 2 * m4 + 18;                        // ≡ 2 (mod 4)
        float w[20];
        load20(slo1, bi, w);
        float4 a, ha, hb;
        conv14_lo_hb(w,     a.x, hb.x); ha.x = conv14_h1a(w);
        conv14_lo_hb(w + 2, a.y, hb.y); ha.y = conv14_h1a(w + 2);
        conv14_lo_hb(w + 4, a.z, hb.z); ha.z = conv14_h1a(w + 4);
        conv14_lo_hb(w + 6, a.w, hb.w); ha.w = conv14_h1a(w + 6);
        __stcs((float4*)(yh1 + m4), ha);
        __stcs((float4*)(yh1 + m4 + L2LEN), hb);
        *(float4*)(slo2 + SW(m4 + H2)) = a;
    }
    __syncthreads();

    // ---- Level 3 (4-wide, N3 = 4*NTH exactly) ----
    const int base3 = tile * N3;
    float* olo = out + (size_t)b * L3LEN + base3;
    float* yh2 = out + OUT_YH2 + (size_t)b * (2u * L3LEN) + base3;
    {
        int m4 = 4 * tid;
        int bi = 2 * m4 + 2;                         // ≡ 2 (mod 4)
        float w[20];
        load20(slo2, bi, w);
        float4 a, ha, hb;
        conv14_lo_hb(w,     a.x, hb.x); ha.x = conv14_h1a(w);
        conv14_lo_hb(w + 2, a.y, hb.y); ha.y = conv14_h1a(w + 2);
        conv14_lo_hb(w + 4, a.z, hb.z); ha.z = conv14_h1a(w + 4);
        conv14_lo_hb(w + 6, a.w, hb.w); ha.w = conv14_h1a(w + 6);
        __stcs((float4*)(olo + m4), a);
        __stcs((float4*)(yh2 + m4), ha);
        __stcs((float4*)(yh2 + m4 + L3LEN), hb);
    }
}

extern "C" void kernel_launch(void* const* d_in, const int* in_sizes, int n_in,
                              void* d_out, int out_size) {
    const float* x = (const float*)d_in[0];
    float* out = (float*)d_out;
    dim3 grid(TILES, BATCH);
    dtcwt_kernel<<<grid, NTH>>>(x, out);
}

// round 12
// speedup vs baseline: 1.0300x; 1.0300x over previous
#include <cuda_runtime.h>

// DTCWT 1D forward, 3 levels, fully fused. x: [64, 1, 2^20] f32.
// Outputs concatenated: lo @0, yh0 @8388608, yh1 @41943040, yh2 @75497472.
// Level 1 from gmem with two independent 4-output groups per iteration
// (8 LDG.128 in flight per thread); lo1/lo2 pyramids in swizzled smem.

#define L0    (1 << 20)
#define L1LEN (L0 >> 1)   // 524288
#define L2LEN (L0 >> 2)   // 262144
#define L3LEN (L0 >> 3)   // 131072
#define BATCH 64

#define TILE_X 8192
#define TILES  (L0 / TILE_X)       // 128
#define N1 (TILE_X / 2)            // 4096
#define N2 (TILE_X / 4)            // 2048
#define N3 (TILE_X / 8)            // 1024
#define H1 24
#define H2 8
#define NTH 256

#define SLO1_SIZE 4160             // (N1+48) padded
#define SLO2_SIZE 2080             // (N2+16) padded
#define SM_TOTAL (SLO1_SIZE + SLO2_SIZE)   // 6240 floats = 24.96 KB

#define OUT_YH0 8388608u
#define OUT_YH1 41943040u
#define OUT_YH2 75497472u

// 2-bit bank swizzle: XOR float-index bits [2,3] with bits [5,6].
__device__ __forceinline__ int SW(int i) { return i ^ ((i >> 3) & 0xC); }

// ---- filters as compile-time immediates (fixed in reference) ----
static __device__ __forceinline__ float conv5_h0o(const float* v) {
    float s = -0.05f * (v[0] + v[4]);
    s = fmaf(0.25f, v[1] + v[3], s);
    s = fmaf(0.6f, v[2], s);
    return s;
}
static __device__ __forceinline__ float conv7_h1o(const float* v) {
    float s = -0.0107143f * (v[0] + v[6]);
    s = fmaf( 0.0535714f, v[1] + v[5], s);
    s = fmaf( 0.2607143f, v[2] + v[4], s);
    s = fmaf(-0.6071429f, v[3], s);
    return s;
}
// h1a[n] = (-1)^n * h0a[13-n]
static __device__ __forceinline__ float conv14_h1a(const float* v) {
    float s = -0.00455690f * v[0];
    s = fmaf( 0.00543948f, v[1],  s);
    s = fmaf( 0.01702522f, v[2],  s);
    s = fmaf(-0.02382538f, v[3],  s);
    s = fmaf(-0.10671180f, v[4],  s);
    s = fmaf(-0.01186609f, v[5],  s);
    s = fmaf( 0.56881042f, v[6],  s);
    s = fmaf(-0.75614564f, v[7],  s);
    s = fmaf( 0.27529538f, v[8],  s);
    s = fmaf( 0.11720389f, v[9],  s);
    s = fmaf(-0.03887280f, v[10], s);
    s = fmaf(-0.03466035f, v[11], s);
    s = fmaf(-0.00388321f, v[12], s);
    s = fmaf(-0.00325314f, v[13], s);
    return s;
}
// lo = conv(h0a), hb = conv(h1b): lo = E + O, hb = O - E (even/odd partial sums).
static __device__ __forceinline__ void conv14_lo_hb(const float* v, float& lo, float& hb) {
    float e =  0.00325314f * v[0];
    e = fmaf( 0.03466035f, v[2],  e);
    e = fmaf(-0.11720389f, v[4],  e);
    e = fmaf( 0.75614564f, v[6],  e);
    e = fmaf( 0.01186609f, v[8],  e);
    e = fmaf( 0.02382538f, v[10], e);
    e = fmaf(-0.00543948f, v[12], e);
    float o = -0.00388321f * v[1];
    o = fmaf(-0.03887280f, v[3],  o);
    o = fmaf( 0.27529538f, v[5],  o);
    o = fmaf( 0.56881042f, v[7],  o);
    o = fmaf(-0.10671180f, v[9],  o);
    o = fmaf( 0.01702522f, v[11], o);
    o = fmaf(-0.00455690f, v[13], o);
    lo = e + o;
    hb = o - e;
}
static __device__ __forceinline__ float conv14_h0a(const float* v) {
    float lo, hb;
    conv14_lo_hb(v, lo, hb);
    return lo;
}

// load 20 floats from swizzled smem, base index ≡ 2 mod 4
static __device__ __forceinline__ void load20(const float* buf, int bi, float* w) {
    *(float2*)(w)      = *(const float2*)(buf + SW(bi));
    *(float4*)(w + 2)  = *(const float4*)(buf + SW(bi + 2));
    *(float4*)(w + 6)  = *(const float4*)(buf + SW(bi + 6));
    *(float4*)(w + 10) = *(const float4*)(buf + SW(bi + 10));
    *(float4*)(w + 14) = *(const float4*)(buf + SW(bi + 14));
    *(float2*)(w + 18) = *(const float2*)(buf + SW(bi + 18));
}

// zero-padded float4 load from x row (element-wise checked; edge tiles only)
static __device__ __forceinline__ float4 ld4_safe(const float* xr, int g) {
    if (g >= 0 && g + 4 <= L0) return *(const float4*)(xr + g);
    float4 v;
    v.x = ((unsigned)(g + 0) < (unsigned)L0) ? xr[g + 0] : 0.0f;
    v.y = ((unsigned)(g + 1) < (unsigned)L0) ? xr[g + 1] : 0.0f;
    v.z = ((unsigned)(g + 2) < (unsigned)L0) ? xr[g + 2] : 0.0f;
    v.w = ((unsigned)(g + 3) < (unsigned)L0) ? xr[g + 3] : 0.0f;
    return v;
}

static __device__ __forceinline__ void load16x(const float* __restrict__ xrow,
                                               int g0, bool interior, float* w) {
    if (interior) {
        const float4* xp = (const float4*)(xrow + g0);
        *(float4*)(w)      = xp[0];
        *(float4*)(w + 4)  = xp[1];
        *(float4*)(w + 8)  = xp[2];
        *(float4*)(w + 12) = xp[3];
    } else {
        *(float4*)(w)      = ld4_safe(xrow, g0);
        *(float4*)(w + 4)  = ld4_safe(xrow, g0 + 4);
        *(float4*)(w + 8)  = ld4_safe(xrow, g0 + 8);
        *(float4*)(w + 12) = ld4_safe(xrow, g0 + 12);
    }
}

static __device__ __forceinline__ void l1_compute(const float* w, float4& lo, float4& hi) {
    lo.x = conv5_h0o(w + 2);  hi.x = conv7_h1o(w + 1);
    lo.y = conv5_h0o(w + 4);  hi.y = conv7_h1o(w + 3);
    lo.z = conv5_h0o(w + 6);  hi.z = conv7_h1o(w + 5);
    lo.w = conv5_h0o(w + 8);  hi.w = conv7_h1o(w + 7);
}

__global__ __launch_bounds__(NTH, 5) void dtcwt_kernel(const float* __restrict__ x,
                                                       float* __restrict__ out) {
    __shared__ __align__(128) float sm[SM_TOTAL];
    float* slo1 = sm;
    float* slo2 = sm + SLO1_SIZE;

    const int tile = blockIdx.x;   // 0..127
    const int b    = blockIdx.y;   // 0..63
    const int tid  = threadIdx.x;

    const float* xrow = x + (size_t)b * L0;
    const int xbase = tile * TILE_X;

    // ---- Level 1: two independent 4-output groups per iteration ----
    const int base1 = tile * N1;
    float* yh0 = out + OUT_YH0 + (size_t)b * L1LEN + base1;

    // lo1 halo (48 entries), zero outside level-1 domain
    if (tid < 2 * H1) {
        int r  = (tid < H1) ? tid : tid + N1;
        int g1 = base1 + (r - H1);
        float v = 0.0f;
        if ((unsigned)g1 < (unsigned)L1LEN) {
            float w[5];
#pragma unroll
            for (int j = 0; j < 5; j++) {
                int p = 2 * g1 - 2 + j;
                w[j] = ((unsigned)p < (unsigned)L0) ? xrow[p] : 0.0f;
            }
            v = conv5_h0o(w);
        }
        slo1[SW(r)] = v;
    }

    const bool interior = (tile > 0) && (tile < TILES - 1);
#pragma unroll 1
    for (int it = 0; it < N1 / (8 * NTH); it++) {   // 2 iters, 2 groups each
        int mA = 4 * tid + it * (8 * NTH);
        int mB = mA + 4 * NTH;                       // independent group
        float wA[16], wB[16];
        load16x(xrow, xbase + 2 * mA - 4, interior, wA);   // 8 LDG.128 in flight
        load16x(xrow, xbase + 2 * mB - 4, interior, wB);
        float4 loA, hiA;
        l1_compute(wA, loA, hiA);
        *(float4*)(slo1 + SW(mA + H1)) = loA;
        __stcs((float4*)(yh0 + mA), hiA);
        float4 loB, hiB;
        l1_compute(wB, loB, hiB);
        *(float4*)(slo1 + SW(mB + H1)) = loB;
        __stcs((float4*)(yh0 + mB), hiB);
    }
    __syncthreads();

    // ---- Level 2 (4-wide, 2 iters) ----
    const int base2 = tile * N2;
    float* yh1 = out + OUT_YH1 + (size_t)b * (2u * L2LEN) + base2;

    if (tid < 2 * H2) {   // lo2 halo (16 entries)
        int r  = (tid < H2) ? tid : tid + N2;
        int g2 = base2 + (r - H2);
        float v = 0.0f;
        if ((unsigned)g2 < (unsigned)L2LEN) {
            float w[14];
#pragma unroll
            for (int j = 0; j < 14; j++) w[j] = slo1[SW(2 * r + 2 + j)];
            v = conv14_h0a(w);
        }
        slo2[SW(r)] = v;
    }
#pragma unroll 1
    for (int it = 0; it < N2 / (4 * NTH); it++) {   // 2 iters, kept rolled
        int m4 = 4 * tid + it * (4 * NTH);
        int bi = 2 * m4 + 18;                        // ≡ 2 (mod 4)
        float w[20];
        load20(slo1, bi, w);
        float4 a, ha, hb;
        conv14_lo_hb(w,     a.x, hb.x); ha.x = conv14_h1a(w);
        conv14_lo_hb(w + 2, a.y, hb.y); ha.y = conv14_h1a(w + 2);
        conv14_lo_hb(w + 4, a.z, hb.z); ha.z = conv14_h1a(w + 4);
        conv14_lo_hb(w + 6, a.w, hb.w); ha.w = conv14_h1a(w + 6);
        __stcs((float4*)(yh1 + m4), ha);
        __stcs((float4*)(yh1 + m4 + L2LEN), hb);
        *(float4*)(slo2 + SW(m4 + H2)) = a;
    }
    __syncthreads();

    // ---- Level 3 (4-wide, N3 = 4*NTH exactly) ----
    const int base3 = tile * N3;
    float* olo = out + (size_t)b * L3LEN + base3;
    float* yh2 = out + OUT_YH2 + (size_t)b * (2u * L3LEN) + base3;
    {
        int m4 = 4 * tid;
        int bi = 2 * m4 + 2;                         // ≡ 2 (mod 4)
        float w[20];
        load20(slo2, bi, w);
        float4 a, ha, hb;
        conv14_lo_hb(w,     a.x, hb.x); ha.x = conv14_h1a(w);
        conv14_lo_hb(w + 2, a.y, hb.y); ha.y = conv14_h1a(w + 2);
        conv14_lo_hb(w + 4, a.z, hb.z); ha.z = conv14_h1a(w + 4);
        conv14_lo_hb(w + 6, a.w, hb.w); ha.w = conv14_h1a(w + 6);
        __stcs((float4*)(olo + m4), a);
        __stcs((float4*)(yh2 + m4), ha);
        __stcs((float4*)(yh2 + m4 + L3LEN), hb);
    }
}

extern "C" void kernel_launch(void* const* d_in, const int* in_sizes, int n_in,
                              void* d_out, int out_size) {
    const float* x = (const float*)d_in[0];
    float* out = (float*)d_out;
    dim3 grid(TILES, BATCH);
    dtcwt_kernel<<<grid, NTH>>>(x, out);
}

// round 13
// speedup vs baseline: 1.1268x; 1.0940x over previous
#include <cuda_runtime.h>

// DTCWT 1D forward, 3 levels, fully fused. x: [64, 1, 2^20] f32.
// Outputs concatenated: lo @0, yh0 @8388608, yh1 @41943040, yh2 @75497472.
// R4 inner code; smaller scheduling quantum: TILE_X=4096, NTH=128, 12 CTAs/SM.

#define L0    (1 << 20)
#define L1LEN (L0 >> 1)   // 524288
#define L2LEN (L0 >> 2)   // 262144
#define L3LEN (L0 >> 3)   // 131072
#define BATCH 64

#define TILE_X 4096
#define TILES  (L0 / TILE_X)       // 256
#define N1 (TILE_X / 2)            // 2048
#define N2 (TILE_X / 4)            // 1024
#define N3 (TILE_X / 8)            // 512
#define H1 24
#define H2 8
#define NTH 128

#define SLO1_SIZE 2112             // (N1+48) padded
#define SLO2_SIZE 1056             // (N2+16) padded
#define SM_TOTAL (SLO1_SIZE + SLO2_SIZE)   // 3168 floats = 12.7 KB

#define OUT_YH0 8388608u
#define OUT_YH1 41943040u
#define OUT_YH2 75497472u

// 2-bit bank swizzle: XOR float-index bits [2,3] with bits [5,6].
__device__ __forceinline__ int SW(int i) { return i ^ ((i >> 3) & 0xC); }

// ---- filters as compile-time immediates (fixed in reference) ----
static __device__ __forceinline__ float conv5_h0o(const float* v) {
    float s = -0.05f * (v[0] + v[4]);
    s = fmaf(0.25f, v[1] + v[3], s);
    s = fmaf(0.6f, v[2], s);
    return s;
}
static __device__ __forceinline__ float conv7_h1o(const float* v) {
    float s = -0.0107143f * (v[0] + v[6]);
    s = fmaf( 0.0535714f, v[1] + v[5], s);
    s = fmaf( 0.2607143f, v[2] + v[4], s);
    s = fmaf(-0.6071429f, v[3], s);
    return s;
}
// h1a[n] = (-1)^n * h0a[13-n]
static __device__ __forceinline__ float conv14_h1a(const float* v) {
    float s = -0.00455690f * v[0];
    s = fmaf( 0.00543948f, v[1],  s);
    s = fmaf( 0.01702522f, v[2],  s);
    s = fmaf(-0.02382538f, v[3],  s);
    s = fmaf(-0.10671180f, v[4],  s);
    s = fmaf(-0.01186609f, v[5],  s);
    s = fmaf( 0.56881042f, v[6],  s);
    s = fmaf(-0.75614564f, v[7],  s);
    s = fmaf( 0.27529538f, v[8],  s);
    s = fmaf( 0.11720389f, v[9],  s);
    s = fmaf(-0.03887280f, v[10], s);
    s = fmaf(-0.03466035f, v[11], s);
    s = fmaf(-0.00388321f, v[12], s);
    s = fmaf(-0.00325314f, v[13], s);
    return s;
}
// lo = conv(h0a), hb = conv(h1b): lo = E + O, hb = O - E (even/odd partial sums).
static __device__ __forceinline__ void conv14_lo_hb(const float* v, float& lo, float& hb) {
    float e =  0.00325314f * v[0];
    e = fmaf( 0.03466035f, v[2],  e);
    e = fmaf(-0.11720389f, v[4],  e);
    e = fmaf( 0.75614564f, v[6],  e);
    e = fmaf( 0.01186609f, v[8],  e);
    e = fmaf( 0.02382538f, v[10], e);
    e = fmaf(-0.00543948f, v[12], e);
    float o = -0.00388321f * v[1];
    o = fmaf(-0.03887280f, v[3],  o);
    o = fmaf( 0.27529538f, v[5],  o);
    o = fmaf( 0.56881042f, v[7],  o);
    o = fmaf(-0.10671180f, v[9],  o);
    o = fmaf( 0.01702522f, v[11], o);
    o = fmaf(-0.00455690f, v[13], o);
    lo = e + o;
    hb = o - e;
}
static __device__ __forceinline__ float conv14_h0a(const float* v) {
    float lo, hb;
    conv14_lo_hb(v, lo, hb);
    return lo;
}

// load 20 floats from swizzled smem, base index ≡ 2 mod 4
static __device__ __forceinline__ void load20(const float* buf, int bi, float* w) {
    *(float2*)(w)      = *(const float2*)(buf + SW(bi));
    *(float4*)(w + 2)  = *(const float4*)(buf + SW(bi + 2));
    *(float4*)(w + 6)  = *(const float4*)(buf + SW(bi + 6));
    *(float4*)(w + 10) = *(const float4*)(buf + SW(bi + 10));
    *(float4*)(w + 14) = *(const float4*)(buf + SW(bi + 14));
    *(float2*)(w + 18) = *(const float2*)(buf + SW(bi + 18));
}

// zero-padded float4 load from x row (element-wise checked; edge tiles only)
static __device__ __forceinline__ float4 ld4_safe(const float* xr, int g) {
    if (g >= 0 && g + 4 <= L0) return *(const float4*)(xr + g);
    float4 v;
    v.x = ((unsigned)(g + 0) < (unsigned)L0) ? xr[g + 0] : 0.0f;
    v.y = ((unsigned)(g + 1) < (unsigned)L0) ? xr[g + 1] : 0.0f;
    v.z = ((unsigned)(g + 2) < (unsigned)L0) ? xr[g + 2] : 0.0f;
    v.w = ((unsigned)(g + 3) < (unsigned)L0) ? xr[g + 3] : 0.0f;
    return v;
}

__global__ __launch_bounds__(NTH, 12) void dtcwt_kernel(const float* __restrict__ x,
                                                        float* __restrict__ out) {
    __shared__ __align__(128) float sm[SM_TOTAL];
    float* slo1 = sm;
    float* slo2 = sm + SLO1_SIZE;

    const int tile = blockIdx.x;   // 0..255
    const int b    = blockIdx.y;   // 0..63
    const int tid  = threadIdx.x;

    const float* xrow = x + (size_t)b * L0;
    const int xbase = tile * TILE_X;

    // ---- Level 1: directly from gmem, 4-wide ----
    const int base1 = tile * N1;
    float* yh0 = out + OUT_YH0 + (size_t)b * L1LEN + base1;

    // lo1 halo (48 entries), zero outside level-1 domain
    if (tid < 2 * H1) {
        int r  = (tid < H1) ? tid : tid + N1;
        int g1 = base1 + (r - H1);
        float v = 0.0f;
        if ((unsigned)g1 < (unsigned)L1LEN) {
            float w[5];
#pragma unroll
            for (int j = 0; j < 5; j++) {
                int p = 2 * g1 - 2 + j;
                w[j] = ((unsigned)p < (unsigned)L0) ? xrow[p] : 0.0f;
            }
            v = conv5_h0o(w);
        }
        slo1[SW(r)] = v;
    }

    const bool interior = (tile > 0) && (tile < TILES - 1);
#pragma unroll 1
    for (int it = 0; it < N1 / (4 * NTH); it++) {   // 4 iters, kept rolled
        int m4 = 4 * tid + it * (4 * NTH);
        int g0 = xbase + 2 * m4 - 4;                 // 16B aligned
        float w[16];
        if (interior) {
            const float4* xp = (const float4*)(xrow + g0);
            *(float4*)(w)      = xp[0];
            *(float4*)(w + 4)  = xp[1];
            *(float4*)(w + 8)  = xp[2];
            *(float4*)(w + 12) = xp[3];
        } else {
            *(float4*)(w)      = ld4_safe(xrow, g0);
            *(float4*)(w + 4)  = ld4_safe(xrow, g0 + 4);
            *(float4*)(w + 8)  = ld4_safe(xrow, g0 + 8);
            *(float4*)(w + 12) = ld4_safe(xrow, g0 + 12);
        }
        // w[j] = x[2*m4 - 4 + j]
        float4 lo, hi;
        lo.x = conv5_h0o(w + 2);  hi.x = conv7_h1o(w + 1);
        lo.y = conv5_h0o(w + 4);  hi.y = conv7_h1o(w + 3);
        lo.z = conv5_h0o(w + 6);  hi.z = conv7_h1o(w + 5);
        lo.w = conv5_h0o(w + 8);  hi.w = conv7_h1o(w + 7);
        *(float4*)(slo1 + SW(m4 + H1)) = lo;
        __stcs((float4*)(yh0 + m4), hi);
    }
    __syncthreads();

    // ---- Level 2 (4-wide, 2 iters) ----
    const int base2 = tile * N2;
    float* yh1 = out + OUT_YH1 + (size_t)b * (2u * L2LEN) + base2;

    if (tid < 2 * H2) {   // lo2 halo (16 entries)
        int r  = (tid < H2) ? tid : tid + N2;
        int g2 = base2 + (r - H2);
        float v = 0.0f;
        if ((unsigned)g2 < (unsigned)L2LEN) {
            float w[14];
#pragma unroll
            for (int j = 0; j < 14; j++) w[j] = slo1[SW(2 * r + 2 + j)];
            v = conv14_h0a(w);
        }
        slo2[SW(r)] = v;
    }
#pragma unroll 1
    for (int it = 0; it < N2 / (4 * NTH); it++) {   // 2 iters, kept rolled
        int m4 = 4 * tid + it * (4 * NTH);
        int bi = 2 * m4 + 18;                        // ≡ 2 (mod 4)
        float w[20];
        load20(slo1, bi, w);
        float4 a, ha, hb;
        conv14_lo_hb(w,     a.x, hb.x); ha.x = conv14_h1a(w);
        conv14_lo_hb(w + 2, a.y, hb.y); ha.y = conv14_h1a(w + 2);
        conv14_lo_hb(w + 4, a.z, hb.z); ha.z = conv14_h1a(w + 4);
        conv14_lo_hb(w + 6, a.w, hb.w); ha.w = conv14_h1a(w + 6);
        __stcs((float4*)(yh1 + m4), ha);
        __stcs((float4*)(yh1 + m4 + L2LEN), hb);
        *(float4*)(slo2 + SW(m4 + H2)) = a;
    }
    __syncthreads();

    // ---- Level 3 (4-wide, N3 = 4*NTH exactly) ----
    const int base3 = tile * N3;
    float* olo = out + (size_t)b * L3LEN + base3;
    float* yh2 = out + OUT_YH2 + (size_t)b * (2u * L3LEN) + base3;
    {
        int m4 = 4 * tid;
        int bi = 2 * m4 + 2;                         // ≡ 2 (mod 4)
        float w[20];
        load20(slo2, bi, w);
        float4 a, ha, hb;
        conv14_lo_hb(w,     a.x, hb.x); ha.x = conv14_h1a(w);
        conv14_lo_hb(w + 2, a.y, hb.y); ha.y = conv14_h1a(w + 2);
        conv14_lo_hb(w + 4, a.z, hb.z); ha.z = conv14_h1a(w + 4);
        conv14_lo_hb(w + 6, a.w, hb.w); ha.w = conv14_h1a(w + 6);
        __stcs((float4*)(olo + m4), a);
        __stcs((float4*)(yh2 + m4), ha);
        __stcs((float4*)(yh2 + m4 + L3LEN), hb);
    }
}

extern "C" void kernel_launch(void* const* d_in, const int* in_sizes, int n_in,
                              void* d_out, int out_size) {
    const float* x = (const float*)d_in[0];
    float* out = (float*)d_out;
    dim3 grid(TILES, BATCH);
    dtcwt_kernel<<<grid, NTH>>>(x, out);
}